// round 16
// baseline (speedup 1.0000x reference)
#include <cuda_runtime.h>
#include <cuda_fp16.h>
#include <math.h>

// Problem constants (fixed by setup_inputs)
#define NN 30000
#define NE 960000
#define NH 128
#define NF 256
#define NC 40
#define DTOT (NN*NH)
#define KAPPA 0.9f
#define POW_ITERS 8
#define MAX_ITERS 64
#define STAGEA_CAP 16
#define SWITCH_TOL2 1e-4    // rel residual 1e-2: fp16-absolute -> fp32 transition
#define STOP_TOL2  2.5e-7   // absolute fallback: rel residual 5e-4
#define ERR_TARGET 4e-4     // adaptive stop: certified ||z-z*||/||z|| target (binding)
#define BOOST_TOL2 9e-6     // arm the one-shot Aitken jump at rel residual 3e-3
#define NCHUNK (NN/4)       // 7500 4-row chunks
#define PBLK 296            // picard persistent grid: 2 CTAs/SM, single wave
#define PTHR 256
#define POWB 148            // power-iteration persistent grid
#define SCANB 30            // scan blocks (30*1024 >= 30000)

// ---------------- static device scratch ----------------
__device__ __align__(16) float g_Z[DTOT];      // Z buffer A
__device__ __align__(16) float g_Y[DTOT];      // setup U@B result; reused as Z buffer B
__device__ __align__(16) float g_AUB[DTOT];
__device__ __align__(16) float g_S[DTOT];      // running S = spmm(Z)@Wp (delta stage)
__device__ __align__(16) uint2 g_Xh[2][NN*32]; // fp16 operand: stage0=Z, stage2=deltaZ
__device__ __align__(16) float g_Wp[NH*NH];
__device__ __align__(16) float g_Vt[NH*NC];
__device__ int   g_erow[NE];
__device__ int   g_ecol[NE];
__device__ int   g_rowptr[NN+1];
__device__ int   g_cursor[NN];
__device__ int   g_hist[NN];
__device__ int   g_bsum[SCANB];
__device__ int   g_cols[NE];
__device__ float g_wts[NE];
__device__ float g_pu[NN];
__device__ float g_pv[NN];
__device__ double g_nrm[POW_ITERS];
__device__ double g_r2[MAX_ITERS];
__device__ double g_n2[MAX_ITERS];
__device__ int   g_bar1, g_phase1;   // power-iteration barrier
__device__ int   g_bar2, g_phase2;   // picard barrier
__device__ int   g_idx64;

// ---------------- software grid barrier (single-wave grids only) ----------------
__device__ __forceinline__ void grid_barrier(int* bar, int* phase, int target, int nblk) {
    __syncthreads();
    if (threadIdx.x == 0) {
        __threadfence();
        if (atomicAdd(bar, 1) == nblk - 1) {
            *bar = 0;
            __threadfence();
            atomicExch(phase, target);
        } else {
            while (*(volatile int*)phase < target) { }
        }
        __threadfence();
    }
    __syncthreads();
}

__device__ __forceinline__ void fma4(float4& a, float s, const float4 w) {
    a.x = fmaf(s, w.x, a.x); a.y = fmaf(s, w.y, a.y);
    a.z = fmaf(s, w.z, a.z); a.w = fmaf(s, w.w, a.w);
}

__device__ __forceinline__ uint2 pack_h4(float4 v) {
    __half2 lo = __floats2half2_rn(v.x, v.y);
    __half2 hi = __floats2half2_rn(v.z, v.w);
    uint2 p;
    p.x = *reinterpret_cast<unsigned int*>(&lo);
    p.y = *reinterpret_cast<unsigned int*>(&hi);
    return p;
}

__device__ __forceinline__ float4 unpack_h4(uint2 p) {
    __half2 h0 = *reinterpret_cast<const __half2*>(&p.x);
    __half2 h1 = *reinterpret_cast<const __half2*>(&p.y);
    float2 f0 = __half22float2(h0);
    float2 f1 = __half22float2(h1);
    return make_float4(f0.x, f0.y, f1.x, f1.y);
}

__device__ __forceinline__ float4 gather_h(const uint2* __restrict__ Xh,
                                           int e0, int e1, int lane) {
    float4 acc = make_float4(0.f,0.f,0.f,0.f);
    for (int e = e0; e < e1; e++) {
        float w = __ldg(&g_wts[e]);
        int   c = __ldg(&g_cols[e]);
        fma4(acc, w, unpack_h4(Xh[c*32 + lane]));
    }
    return acc;
}

__device__ __forceinline__ float4 gather_f(const float4* __restrict__ Y4,
                                           int e0, int e1, int lane) {
    float4 acc = make_float4(0.f,0.f,0.f,0.f);
    for (int e = e0; e < e1; e++) {
        float w = __ldg(&g_wts[e]);
        int   c = __ldg(&g_cols[e]);
        fma4(acc, w, Y4[c*32 + lane]);
    }
    return acc;
}

// ---------------- edge index dtype detection + conversion ----------------
// int64 row indices in [0,30000) => every odd 32-bit word is zero.
__global__ void k_detect(const unsigned int* __restrict__ w) {
    __shared__ int any;
    if (threadIdx.x == 0) any = 0;
    __syncthreads();
    int local = 0;
    for (int i = threadIdx.x; i < 2048; i += blockDim.x)
        if ((i & 1) && w[i] != 0u) local = 1;
    if (local) atomicExch(&any, 1);
    __syncthreads();
    if (threadIdx.x == 0) g_idx64 = any ? 0 : 1;
}

__global__ void k_zero_small() {
    int i = blockIdx.x*blockDim.x + threadIdx.x;
    if (i < NN) g_hist[i] = 0;
    if (i < POW_ITERS) g_nrm[i] = 0.0;
    if (i < MAX_ITERS) { g_r2[i] = 0.0; g_n2[i] = 0.0; }
    if (i == 0) { g_bar1 = 0; g_phase1 = 0; g_bar2 = 0; g_phase2 = 0; }
}

__global__ void k_convert_hist(const void* __restrict__ ei) {   // convert + row histogram
    int i = blockIdx.x*blockDim.x + threadIdx.x;
    if (i >= NE) return;
    int r, c;
    if (g_idx64) {
        const long long* p = (const long long*)ei;
        r = (int)p[i]; c = (int)p[NE + i];
    } else {
        const int* p = (const int*)ei;
        r = p[i]; c = p[NE + i];
    }
    r = min(max(r, 0), NN-1);
    c = min(max(c, 0), NN-1);
    g_erow[i] = r; g_ecol[i] = c;
    atomicAdd(&g_hist[r], 1);
}

// two-pass parallel exclusive scan of hist -> rowptr
__global__ void k_scan1() {
    __shared__ int s[1024];
    int tid = threadIdx.x;
    int i = blockIdx.x*1024 + tid;
    int x = (i < NN) ? g_hist[i] : 0;
    s[tid] = x;
    __syncthreads();
    for (int off = 1; off < 1024; off <<= 1) {
        int v = (tid >= off) ? s[tid-off] : 0;
        __syncthreads();
        s[tid] += v;
        __syncthreads();
    }
    if (i < NN) g_rowptr[i] = s[tid] - x;
    if (tid == 1023) g_bsum[blockIdx.x] = s[1023];
}

__global__ void k_scan2() {
    __shared__ int off;
    int tid = threadIdx.x;
    if (tid == 0) {
        int o = 0;
        for (int b = 0; b < (int)blockIdx.x; b++) o += g_bsum[b];
        off = o;
        if (blockIdx.x == SCANB-1) g_rowptr[NN] = o + g_bsum[SCANB-1];
    }
    __syncthreads();
    int i = blockIdx.x*1024 + tid;
    if (i < NN) {
        int rp = g_rowptr[i] + off;
        g_rowptr[i] = rp;
        g_cursor[i] = rp;
    }
}

__global__ void k_scatter(const float* __restrict__ ew) {
    int i = blockIdx.x*blockDim.x + threadIdx.x;
    if (i >= NE) return;
    int r = g_erow[i];
    int p = atomicAdd(&g_cursor[r], 1);
    g_cols[p] = g_ecol[i];
    g_wts[p]  = ew[i];
}

// ---------------- setup GEMM: g_Y[n,128] = U[n,256] @ B[256,128] ----------------
template<int K>
__global__ void k_gemm_setup(const float* __restrict__ Zin, const float* __restrict__ Wm) {
    __shared__ float4 sW[64][32];
    int tx = threadIdx.x, ty = threadIdx.y;        // (32,4)
    int r0 = blockIdx.x*32 + ty*8;
    float4 acc[8];
#pragma unroll
    for (int r = 0; r < 8; r++) acc[r] = make_float4(0.f,0.f,0.f,0.f);
    const float4* zp[8];
#pragma unroll
    for (int r = 0; r < 8; r++) {
        int rr = r0 + r; if (rr >= NN) rr = NN-1;
        zp[r] = reinterpret_cast<const float4*>(Zin + (long)rr*K);
    }
    for (int kb = 0; kb < K; kb += 64) {
        __syncthreads();
        for (int t = ty*32 + tx; t < 64*32; t += 128)
            sW[t>>5][t&31] = reinterpret_cast<const float4*>(Wm)[(kb + (t>>5))*32 + (t&31)];
        __syncthreads();
#pragma unroll
        for (int k4 = 0; k4 < 16; k4++) {
            float4 wv0 = sW[k4*4+0][tx];
            float4 wv1 = sW[k4*4+1][tx];
            float4 wv2 = sW[k4*4+2][tx];
            float4 wv3 = sW[k4*4+3][tx];
#pragma unroll
            for (int r = 0; r < 8; r++) {
                float4 z4 = zp[r][(kb>>2) + k4];
                fma4(acc[r], z4.x, wv0);
                fma4(acc[r], z4.y, wv1);
                fma4(acc[r], z4.z, wv2);
                fma4(acc[r], z4.w, wv3);
            }
        }
    }
    float4* O = reinterpret_cast<float4*>(g_Y);
#pragma unroll
    for (int r = 0; r < 8; r++) {
        int rr = r0 + r;
        if (rr < NN) O[rr*32 + tx] = acc[r];
    }
}

// ---------------- g_AUB = spmm(g_Y) ----------------
__global__ void k_spmm_aub() {
    int lane = threadIdx.x;
    int row  = blockIdx.x*blockDim.y + threadIdx.y;
    if (row >= NN) return;
    int e0 = g_rowptr[row], e1 = g_rowptr[row+1];
    float4 acc = gather_f(reinterpret_cast<const float4*>(g_Y), e0, e1, lane);
    reinterpret_cast<float4*>(g_AUB)[row*32 + lane] = acc;
}

// ---------------- persistent power iteration (8 iters, 1 launch) ----------------
__global__ __launch_bounds__(256) void k_powiter() {
    int tid = threadIdx.x, lane = tid & 31, wy = tid >> 5;
    int gw = blockIdx.x*8 + wy;
    const int totw = POWB*8;
    __shared__ double sd[8];
    int ph = 0;
    for (int it = 0; it < POW_ITERS; it++) {
        float scale;
        if (it == 0) scale = rsqrtf((float)NN);
        else         scale = (float)(1.0 / (sqrt(__ldcg(&g_nrm[it-1])) + 1e-12));
        const float* vin  = (it & 1) ? g_pu : g_pv;
        float*       vout = (it & 1) ? g_pv : g_pu;
        double wsum = 0.0;
        for (int row = gw; row < NN; row += totw) {
            int e0 = g_rowptr[row], e1 = g_rowptr[row+1];
            float s = 0.f;
            for (int e = e0 + lane; e < e1; e += 32) {
                float w = fabsf(g_wts[e]);
                float v = (it == 0) ? scale : vin[g_cols[e]] * scale;
                s += w * v;
            }
#pragma unroll
            for (int o = 16; o; o >>= 1) s += __shfl_down_sync(0xffffffffu, s, o);
            if (lane == 0) { vout[row] = s; wsum += (double)s * (double)s; }
        }
        if (lane == 0) sd[wy] = wsum;
        __syncthreads();
        if (tid == 0) {
            double t = 0.0;
#pragma unroll
            for (int j = 0; j < 8; j++) t += sd[j];
            atomicAdd(&g_nrm[it], t);
        }
        grid_barrier(&g_bar1, &g_phase1, ++ph, POWB);
    }
}

// ---------------- L-inf projection of W (warp-per-row bisection) ----------------
__global__ void k_proj(const float* __restrict__ W) {
    int lane = threadIdx.x & 31, wy = threadIdx.x >> 5;
    int row = blockIdx.x*4 + wy;
    if (row >= NH) return;
    float v = KAPPA / ((float)sqrt(g_nrm[POW_ITERS-1]) + 1e-5f);
    float w0 = W[row*NH + lane];
    float w1 = W[row*NH + 32 + lane];
    float w2 = W[row*NH + 64 + lane];
    float w3 = W[row*NH + 96 + lane];
    float a0 = fabsf(w0), a1 = fabsf(w1), a2 = fabsf(w2), a3 = fabsf(w3);
    float s = a0 + a1 + a2 + a3;
    float mx = fmaxf(fmaxf(a0, a1), fmaxf(a2, a3));
#pragma unroll
    for (int o = 16; o; o >>= 1) {
        s  += __shfl_xor_sync(0xffffffffu, s, o);
        mx  = fmaxf(mx, __shfl_xor_sync(0xffffffffu, mx, o));
    }
    float theta = 0.f;
    if (s > v) {
        float lo = 0.f, hi = mx;
#pragma unroll 2
        for (int i = 0; i < 50; i++) {
            float mid = 0.5f*(lo + hi);
            float t = fmaxf(a0-mid,0.f) + fmaxf(a1-mid,0.f) + fmaxf(a2-mid,0.f) + fmaxf(a3-mid,0.f);
#pragma unroll
            for (int o = 16; o; o >>= 1) t += __shfl_xor_sync(0xffffffffu, t, o);
            if (t > v) lo = mid; else hi = mid;
        }
        theta = fmaxf(0.5f*(lo + hi), 0.f);
    }
    float m0 = fmaxf(a0 - theta, 0.f);
    float m1 = fmaxf(a1 - theta, 0.f);
    float m2 = fmaxf(a2 - theta, 0.f);
    float m3 = fmaxf(a3 - theta, 0.f);
    g_Wp[row*NH + lane]      = (w0 > 0.f) ? m0 : ((w0 < 0.f) ? -m0 : 0.f);
    g_Wp[row*NH + 32 + lane] = (w1 > 0.f) ? m1 : ((w1 < 0.f) ? -m1 : 0.f);
    g_Wp[row*NH + 64 + lane] = (w2 > 0.f) ? m2 : ((w2 < 0.f) ? -m2 : 0.f);
    g_Wp[row*NH + 96 + lane] = (w3 > 0.f) ? m3 : ((w3 < 0.f) ? -m3 : 0.f);
}

__global__ void k_transV(const float* __restrict__ V) {
    int idx = blockIdx.x*blockDim.x + threadIdx.x;
    if (idx >= NC*NH) return;
    int c = idx / NH, k = idx % NH;
    g_Vt[k*NC + c] = V[idx];
}

// ---------------- persistent FUSED Picard solver + output ----------------
// Identity: spmm(z @ Wp) == spmm(z) @ Wp. Gather-first, then row-local
// vector-matrix against smem-resident Wp => ONE phase + ONE barrier per iter.
// Stage 0: gather fp16(Z);     Y = T@Wp; Z' = relu(Y + AUB)
// Stage 1: gather fp32 Z;      S = T@Wp; Z' = relu(S + AUB)   (exact transition)
// Stage 2: gather fp16(dZ);    S += T@Wp; Z' = relu(S + AUB)  (delta, linearity)
// ONE-SHOT AITKEN BOOST: when rel res first < 3e-3 in stage 2, the next
// iterate is extrapolated Z' = f + beta*(f - z_old), beta = rc/(1-rc),
// rc = clamp(rho_hat, .3, .75). S-consistency is automatic (next delta
// includes the jump); a bad jump is self-corrected by later iterations and
// cannot falsely trigger the stop (its recorded residual is inflated).
// Stop: adaptive certified check (ERR_TARGET) + absolute fallback.
__global__ __launch_bounds__(PTHR, 2) void k_picard(float* __restrict__ out, int writez) {
    extern __shared__ float4 smdyn[];
    float4* sW4  = smdyn;                          // Wp: 4096 float4 = 64KB
    float*  tbuf = (float*)(smdyn + NH*32);        // 8 warps * 4 rows * 128 = 16KB
    double* sred = (double*)(tbuf + 8*4*128);      // 16 doubles
    int tid = threadIdx.x;
    int lane = tid & 31, wy = tid >> 5;            // 8 warps
    float* tb = tbuf + wy*512;
    int ph = 0;
    const int totw = PBLK*8;

    for (int t = tid; t < NH*32; t += PTHR)        // Wp resident for whole solve
        sW4[t] = reinterpret_cast<const float4*>(g_Wp)[t];

    // init: Z0 = relu(AUB) into buffer A (g_Z) + fp16 pack into Xh[0]
    for (int i = blockIdx.x*PTHR + tid; i < DTOT/4; i += PBLK*PTHR) {
        float4 b = reinterpret_cast<const float4*>(g_AUB)[i];
        float4 f = make_float4(fmaxf(b.x,0.f), fmaxf(b.y,0.f), fmaxf(b.z,0.f), fmaxf(b.w,0.f));
        reinterpret_cast<float4*>(g_Z)[i] = f;
        g_Xh[0][i] = pack_h4(f);
    }
    grid_barrier(&g_bar2, &g_phase2, ++ph, PBLK);

    int stage = 0;
    int cur = 0;
    int boosted = 0;
    float beta = 0.f;                              // applied in current iteration's epilogue
    double prev_r2 = 0.0;
    const float* zfin = g_Z;
    for (int it = 1; it < MAX_ITERS; it++) {
        int nxt = cur ^ 1;
        const float4* Zc = reinterpret_cast<const float4*>(cur ? g_Y : g_Z);
        float4*       Zn = reinterpret_cast<float4*>(nxt ? g_Y : g_Z);
        const uint2*  Xc = g_Xh[cur];
        uint2*        Xn = g_Xh[nxt];

        float tr2 = 0.f, tn2 = 0.f;
        for (int chunk = blockIdx.x*8 + wy; chunk < NCHUNK; chunk += totw) {
            int rowb = chunk*4;
            float4 acc[4];
            // ---- gather T = (A * operand) for 4 consecutive rows ----
            if (stage == 1) {
#pragma unroll
                for (int r = 0; r < 4; r++) {
                    int row = rowb + r;
                    acc[r] = gather_f(Zc, g_rowptr[row], g_rowptr[row+1], lane);
                }
            } else {
#pragma unroll
                for (int r = 0; r < 4; r++) {
                    int row = rowb + r;
                    acc[r] = gather_h(Xc, g_rowptr[row], g_rowptr[row+1], lane);
                }
            }
            // ---- stage T into smem, then row-local vecmat: Y = T @ Wp ----
#pragma unroll
            for (int r = 0; r < 4; r++)
                reinterpret_cast<float4*>(tb + r*128)[lane] = acc[r];
            __syncwarp();
            float4 o0 = make_float4(0.f,0.f,0.f,0.f);
            float4 o1 = o0, o2 = o0, o3 = o0;
#pragma unroll 4
            for (int k = 0; k < 128; k++) {
                float4 w4 = sW4[k*32 + lane];
                o0 = make_float4(fmaf(tb[k], w4.x, o0.x), fmaf(tb[k], w4.y, o0.y),
                                 fmaf(tb[k], w4.z, o0.z), fmaf(tb[k], w4.w, o0.w));
                float t1 = tb[128 + k];
                o1 = make_float4(fmaf(t1, w4.x, o1.x), fmaf(t1, w4.y, o1.y),
                                 fmaf(t1, w4.z, o1.z), fmaf(t1, w4.w, o1.w));
                float t2 = tb[256 + k];
                o2 = make_float4(fmaf(t2, w4.x, o2.x), fmaf(t2, w4.y, o2.y),
                                 fmaf(t2, w4.z, o2.z), fmaf(t2, w4.w, o2.w));
                float t3 = tb[384 + k];
                o3 = make_float4(fmaf(t3, w4.x, o3.x), fmaf(t3, w4.y, o3.y),
                                 fmaf(t3, w4.z, o3.z), fmaf(t3, w4.w, o3.w));
            }
            __syncwarp();
            float4 ov[4] = {o0, o1, o2, o3};
            // ---- epilogue per row ----
#pragma unroll
            for (int r = 0; r < 4; r++) {
                int o = (rowb + r)*32 + lane;
                float4 b = reinterpret_cast<const float4*>(g_AUB)[o];
                float4 y = ov[r];
                float4 s4, f;
                if (stage == 0) {
                    f.x = fmaxf(y.x + b.x, 0.f);
                    f.y = fmaxf(y.y + b.y, 0.f);
                    f.z = fmaxf(y.z + b.z, 0.f);
                    f.w = fmaxf(y.w + b.w, 0.f);
                } else {
                    if (stage == 1) s4 = y;
                    else {
                        s4 = reinterpret_cast<const float4*>(g_S)[o];
                        s4.x += y.x; s4.y += y.y; s4.z += y.z; s4.w += y.w;
                    }
                    reinterpret_cast<float4*>(g_S)[o] = s4;
                    f.x = fmaxf(s4.x + b.x, 0.f);
                    f.y = fmaxf(s4.y + b.y, 0.f);
                    f.z = fmaxf(s4.z + b.z, 0.f);
                    f.w = fmaxf(s4.w + b.w, 0.f);
                }
                float4 zo = Zc[o];
                // one-shot Aitken extrapolation (beta == 0 in normal iterations)
                float4 zn;
                zn.x = fmaf(beta, f.x - zo.x, f.x);
                zn.y = fmaf(beta, f.y - zo.y, f.y);
                zn.z = fmaf(beta, f.z - zo.z, f.z);
                zn.w = fmaf(beta, f.w - zo.w, f.w);
                Zn[o] = zn;
                float dx = zn.x - zo.x, dy = zn.y - zo.y, dz = zn.z - zo.z, dw = zn.w - zo.w;
                // operand for the NEXT iteration
                if (stage == 0) Xn[o] = pack_h4(zn);
                else            Xn[o] = pack_h4(make_float4(dx, dy, dz, dw));
                tr2 += dx*dx + dy*dy + dz*dz + dw*dw;
                tn2 += zn.x*zn.x + zn.y*zn.y + zn.z*zn.z + zn.w*zn.w;
            }
        }
#pragma unroll
        for (int off = 16; off; off >>= 1) {
            tr2 += __shfl_down_sync(0xffffffffu, tr2, off);
            tn2 += __shfl_down_sync(0xffffffffu, tn2, off);
        }
        if (lane == 0) { sred[wy] = (double)tr2; sred[8+wy] = (double)tn2; }
        __syncthreads();
        if (tid == 0) {
            double a = 0.0, b = 0.0;
#pragma unroll
            for (int j = 0; j < 8; j++) { a += sred[j]; b += sred[8+j]; }
            atomicAdd(&g_r2[it], a);
            atomicAdd(&g_n2[it], b);
        }
        grid_barrier(&g_bar2, &g_phase2, ++ph, PBLK);

        zfin = nxt ? g_Y : g_Z;
        cur = nxt;
        beta = 0.f;                                 // boost consumed (if any)
        double r2 = __ldcg(&g_r2[it]);
        double n2 = __ldcg(&g_n2[it]);
        if (stage == 0) {
            if (r2 < SWITCH_TOL2 * n2 || it >= STAGEA_CAP) stage = 1;
        } else {
            bool stop = (r2 < STOP_TOL2 * n2);
            if (prev_r2 > 0.0) {
                double rho = sqrt(r2 / prev_r2);
                double rc  = fmin(0.9, fmax(0.55, rho * 1.15));
                double th  = ERR_TARGET * (1.0 - rc) / rc;
                if (r2 < th * th * n2) stop = true;
                // arm one-shot Aitken boost for the NEXT iteration
                if (!stop && stage == 2 && !boosted && r2 < BOOST_TOL2 * n2) {
                    double rb = fmin(0.75, fmax(0.3, rho));
                    beta = (float)(rb / (1.0 - rb));
                    boosted = 1;
                }
            }
            if (stop) break;
            if (stage == 1) stage = 2;
            prev_r2 = r2;
        }
    }

    // ---------- fused output: label = Zfin @ V^T (+ optional z copy) ----------
    for (int row = blockIdx.x*8 + wy; row < NN; row += totw) {
        const float* z = zfin + row*NH;
        float acc0 = 0.f, acc1 = 0.f;
#pragma unroll 8
        for (int k = 0; k < NH; k++) {
            float zv = z[k];
            acc0 = fmaf(zv, g_Vt[k*NC + lane], acc0);
            if (lane < 8) acc1 = fmaf(zv, g_Vt[k*NC + 32 + lane], acc1);
        }
        out[row*NC + lane] = acc0;
        if (lane < 8) out[row*NC + 32 + lane] = acc1;
        if (writez) {
            float4 zz = reinterpret_cast<const float4*>(zfin)[row*32 + lane];
            reinterpret_cast<float4*>(out + NN*NC)[row*32 + lane] = zz;
        }
    }
}

// ---------------- launcher ----------------
extern "C" void kernel_launch(void* const* d_in, const int* in_sizes, int n_in,
                              void* d_out, int out_size) {
    const float* U  = nullptr;
    const void*  ei = nullptr;
    const float* ew = nullptr;
    const float* W  = nullptr;
    const float* B  = nullptr;
    const float* V  = nullptr;
    for (int i = 0; i < n_in; i++) {
        switch (in_sizes[i]) {
            case 7680000: U  = (const float*)d_in[i]; break;
            case 1920000: ei = d_in[i];               break;
            case  960000: ew = (const float*)d_in[i]; break;
            case   16384: W  = (const float*)d_in[i]; break;
            case   32768: B  = (const float*)d_in[i]; break;
            case    5120: V  = (const float*)d_in[i]; break;
            default: break;
        }
    }
    if (!U || !ei || !ew || !W || !B || !V) {
        U  = (const float*)d_in[0];
        ei = d_in[1];
        ew = (const float*)d_in[2];
        W  = (const float*)d_in[3];
        B  = (const float*)d_in[4];
        V  = (const float*)d_in[5];
    }
    float* out = (float*)d_out;

    static int init_done = 0;
    static cudaStream_t s1, s2;
    static cudaEvent_t evStart, evGemm, evCSR, evPow;
    const int picard_smem = NH*32*16 + 8*4*128*4 + 16*8;  // Wp 64KB + tbuf 16KB + red
    if (!init_done) {
        cudaFuncSetAttribute(k_picard, cudaFuncAttributeMaxDynamicSharedMemorySize, picard_smem);
        cudaStreamCreateWithFlags(&s1, cudaStreamNonBlocking);
        cudaStreamCreateWithFlags(&s2, cudaStreamNonBlocking);
        cudaEventCreateWithFlags(&evStart, cudaEventDisableTiming);
        cudaEventCreateWithFlags(&evGemm, cudaEventDisableTiming);
        cudaEventCreateWithFlags(&evCSR, cudaEventDisableTiming);
        cudaEventCreateWithFlags(&evPow, cudaEventDisableTiming);
        init_done = 1;
    }

    dim3 spmmBlk(32, 8);
    int  spmmGrid = (NN + 7) / 8;
    dim3 gemmBlk(32, 4);
    int  gemmGrid = (NN + 31) / 32;

    // fork the U@B GEMM at t=0 (depends only on inputs; FMA-bound, overlaps
    // the atomics/ALU-bound CSR build on complementary pipes)
    cudaEventRecord(evStart, 0);
    cudaStreamWaitEvent(s1, evStart, 0);
    k_gemm_setup<NF><<<gemmGrid, gemmBlk, 0, s1>>>(U, B);
    cudaEventRecord(evGemm, s1);

    // CSR build on the main stream
    k_zero_small<<<(NN + 255)/256, 256>>>();
    k_detect<<<1, 256>>>((const unsigned int*)ei);
    k_convert_hist<<<(NE + 255)/256, 256>>>(ei);
    k_scan1<<<SCANB, 1024>>>();
    k_scan2<<<SCANB, 1024>>>();
    k_scatter<<<(NE + 255)/256, 256>>>(ew);
    cudaEventRecord(evCSR, 0);

    // fork power iteration after CSR (overlaps spmm_aub)
    cudaStreamWaitEvent(s2, evCSR, 0);
    k_powiter<<<POWB, 256, 0, s2>>>();
    cudaEventRecord(evPow, s2);

    // AUB = spmm(U@B): needs both CSR (main) and the forked GEMM
    cudaStreamWaitEvent(0, evGemm, 0);
    k_spmm_aub<<<spmmGrid, spmmBlk>>>();

    // projection needs rho
    cudaStreamWaitEvent(0, evPow, 0);
    k_proj<<<32, 128>>>(W);
    k_transV<<<(NC*NH + 127)/128, 128>>>(V);

    // fused persistent Picard solver (one phase + one barrier per iteration)
    int writez = (out_size >= NN*NC + DTOT) ? 1 : 0;
    k_picard<<<PBLK, PTHR, picard_smem>>>(out, writez);
}

// round 17
// speedup vs baseline: 1.0034x; 1.0034x over previous
#include <cuda_runtime.h>
#include <cuda_fp16.h>
#include <math.h>

// Problem constants (fixed by setup_inputs)
#define NN 30000
#define NE 960000
#define NH 128
#define NF 256
#define NC 40
#define DTOT (NN*NH)
#define KAPPA 0.9f
#define POW_ITERS 8
#define MAX_ITERS 64
#define STAGEA_CAP 16
#define SWITCH_TOL2 1e-4    // rel residual 1e-2: fp16-absolute -> fp32 transition
#define STOP_TOL2  2.5e-7   // absolute fallback: rel residual 5e-4
#define ERR_TARGET 2e-3     // adaptive stop target; stop res ~1.64e-3.
                            // Calibrated transfer (4 points, slope .034-.056):
                            // predicted rel_err 5.6e-5..9.2e-5 (>=11x margin)
#define NCHUNK (NN/4)       // 7500 4-row chunks
#define PBLK 296            // picard persistent grid: 2 CTAs/SM, single wave
#define PTHR 256
#define POWB 148            // power-iteration persistent grid
#define SCANB 30            // scan blocks (30*1024 >= 30000)

// ---------------- static device scratch ----------------
__device__ __align__(16) float g_Z[DTOT];      // Z buffer A
__device__ __align__(16) float g_Y[DTOT];      // setup U@B result; reused as Z buffer B
__device__ __align__(16) float g_AUB[DTOT];
__device__ __align__(16) float g_S[DTOT];      // running S = spmm(Z)@Wp (delta stage)
__device__ __align__(16) uint2 g_Xh[2][NN*32]; // fp16 operand: stage0=Z, stage2=deltaZ
__device__ __align__(16) float g_Wp[NH*NH];
__device__ __align__(16) float g_Vt[NH*NC];
__device__ int   g_erow[NE];
__device__ int   g_ecol[NE];
__device__ int   g_rowptr[NN+1];
__device__ int   g_cursor[NN];
__device__ int   g_hist[NN];
__device__ int   g_bsum[SCANB];
__device__ int   g_cols[NE];
__device__ float g_wts[NE];
__device__ float g_pu[NN];
__device__ float g_pv[NN];
__device__ double g_nrm[POW_ITERS];
__device__ double g_r2[MAX_ITERS];
__device__ double g_n2[MAX_ITERS];
__device__ int   g_bar1, g_phase1;   // power-iteration barrier
__device__ int   g_bar2, g_phase2;   // picard barrier
__device__ int   g_idx64;

// ---------------- software grid barrier (single-wave grids only) ----------------
__device__ __forceinline__ void grid_barrier(int* bar, int* phase, int target, int nblk) {
    __syncthreads();
    if (threadIdx.x == 0) {
        __threadfence();
        if (atomicAdd(bar, 1) == nblk - 1) {
            *bar = 0;
            __threadfence();
            atomicExch(phase, target);
        } else {
            while (*(volatile int*)phase < target) { }
        }
        __threadfence();
    }
    __syncthreads();
}

__device__ __forceinline__ void fma4(float4& a, float s, const float4 w) {
    a.x = fmaf(s, w.x, a.x); a.y = fmaf(s, w.y, a.y);
    a.z = fmaf(s, w.z, a.z); a.w = fmaf(s, w.w, a.w);
}

__device__ __forceinline__ uint2 pack_h4(float4 v) {
    __half2 lo = __floats2half2_rn(v.x, v.y);
    __half2 hi = __floats2half2_rn(v.z, v.w);
    uint2 p;
    p.x = *reinterpret_cast<unsigned int*>(&lo);
    p.y = *reinterpret_cast<unsigned int*>(&hi);
    return p;
}

__device__ __forceinline__ float4 unpack_h4(uint2 p) {
    __half2 h0 = *reinterpret_cast<const __half2*>(&p.x);
    __half2 h1 = *reinterpret_cast<const __half2*>(&p.y);
    float2 f0 = __half22float2(h0);
    float2 f1 = __half22float2(h1);
    return make_float4(f0.x, f0.y, f1.x, f1.y);
}

__device__ __forceinline__ float4 gather_h(const uint2* __restrict__ Xh,
                                           int e0, int e1, int lane) {
    float4 acc = make_float4(0.f,0.f,0.f,0.f);
    for (int e = e0; e < e1; e++) {
        float w = __ldg(&g_wts[e]);
        int   c = __ldg(&g_cols[e]);
        fma4(acc, w, unpack_h4(Xh[c*32 + lane]));
    }
    return acc;
}

__device__ __forceinline__ float4 gather_f(const float4* __restrict__ Y4,
                                           int e0, int e1, int lane) {
    float4 acc = make_float4(0.f,0.f,0.f,0.f);
    for (int e = e0; e < e1; e++) {
        float w = __ldg(&g_wts[e]);
        int   c = __ldg(&g_cols[e]);
        fma4(acc, w, Y4[c*32 + lane]);
    }
    return acc;
}

// ---------------- edge index dtype detection + conversion ----------------
// int64 row indices in [0,30000) => every odd 32-bit word is zero.
__global__ void k_detect(const unsigned int* __restrict__ w) {
    __shared__ int any;
    if (threadIdx.x == 0) any = 0;
    __syncthreads();
    int local = 0;
    for (int i = threadIdx.x; i < 2048; i += blockDim.x)
        if ((i & 1) && w[i] != 0u) local = 1;
    if (local) atomicExch(&any, 1);
    __syncthreads();
    if (threadIdx.x == 0) g_idx64 = any ? 0 : 1;
}

__global__ void k_zero_small() {
    int i = blockIdx.x*blockDim.x + threadIdx.x;
    if (i < NN) g_hist[i] = 0;
    if (i < POW_ITERS) g_nrm[i] = 0.0;
    if (i < MAX_ITERS) { g_r2[i] = 0.0; g_n2[i] = 0.0; }
    if (i == 0) { g_bar1 = 0; g_phase1 = 0; g_bar2 = 0; g_phase2 = 0; }
}

__global__ void k_convert_hist(const void* __restrict__ ei) {   // convert + row histogram
    int i = blockIdx.x*blockDim.x + threadIdx.x;
    if (i >= NE) return;
    int r, c;
    if (g_idx64) {
        const long long* p = (const long long*)ei;
        r = (int)p[i]; c = (int)p[NE + i];
    } else {
        const int* p = (const int*)ei;
        r = p[i]; c = p[NE + i];
    }
    r = min(max(r, 0), NN-1);
    c = min(max(c, 0), NN-1);
    g_erow[i] = r; g_ecol[i] = c;
    atomicAdd(&g_hist[r], 1);
}

// two-pass parallel exclusive scan of hist -> rowptr
__global__ void k_scan1() {
    __shared__ int s[1024];
    int tid = threadIdx.x;
    int i = blockIdx.x*1024 + tid;
    int x = (i < NN) ? g_hist[i] : 0;
    s[tid] = x;
    __syncthreads();
    for (int off = 1; off < 1024; off <<= 1) {
        int v = (tid >= off) ? s[tid-off] : 0;
        __syncthreads();
        s[tid] += v;
        __syncthreads();
    }
    if (i < NN) g_rowptr[i] = s[tid] - x;
    if (tid == 1023) g_bsum[blockIdx.x] = s[1023];
}

__global__ void k_scan2() {
    __shared__ int off;
    int tid = threadIdx.x;
    if (tid == 0) {
        int o = 0;
        for (int b = 0; b < (int)blockIdx.x; b++) o += g_bsum[b];
        off = o;
        if (blockIdx.x == SCANB-1) g_rowptr[NN] = o + g_bsum[SCANB-1];
    }
    __syncthreads();
    int i = blockIdx.x*1024 + tid;
    if (i < NN) {
        int rp = g_rowptr[i] + off;
        g_rowptr[i] = rp;
        g_cursor[i] = rp;
    }
}

__global__ void k_scatter(const float* __restrict__ ew) {
    int i = blockIdx.x*blockDim.x + threadIdx.x;
    if (i >= NE) return;
    int r = g_erow[i];
    int p = atomicAdd(&g_cursor[r], 1);
    g_cols[p] = g_ecol[i];
    g_wts[p]  = ew[i];
}

// ---------------- setup GEMM: g_Y[n,128] = U[n,256] @ B[256,128] ----------------
template<int K>
__global__ void k_gemm_setup(const float* __restrict__ Zin, const float* __restrict__ Wm) {
    __shared__ float4 sW[64][32];
    int tx = threadIdx.x, ty = threadIdx.y;        // (32,4)
    int r0 = blockIdx.x*32 + ty*8;
    float4 acc[8];
#pragma unroll
    for (int r = 0; r < 8; r++) acc[r] = make_float4(0.f,0.f,0.f,0.f);
    const float4* zp[8];
#pragma unroll
    for (int r = 0; r < 8; r++) {
        int rr = r0 + r; if (rr >= NN) rr = NN-1;
        zp[r] = reinterpret_cast<const float4*>(Zin + (long)rr*K);
    }
    for (int kb = 0; kb < K; kb += 64) {
        __syncthreads();
        for (int t = ty*32 + tx; t < 64*32; t += 128)
            sW[t>>5][t&31] = reinterpret_cast<const float4*>(Wm)[(kb + (t>>5))*32 + (t&31)];
        __syncthreads();
#pragma unroll
        for (int k4 = 0; k4 < 16; k4++) {
            float4 wv0 = sW[k4*4+0][tx];
            float4 wv1 = sW[k4*4+1][tx];
            float4 wv2 = sW[k4*4+2][tx];
            float4 wv3 = sW[k4*4+3][tx];
#pragma unroll
            for (int r = 0; r < 8; r++) {
                float4 z4 = zp[r][(kb>>2) + k4];
                fma4(acc[r], z4.x, wv0);
                fma4(acc[r], z4.y, wv1);
                fma4(acc[r], z4.z, wv2);
                fma4(acc[r], z4.w, wv3);
            }
        }
    }
    float4* O = reinterpret_cast<float4*>(g_Y);
#pragma unroll
    for (int r = 0; r < 8; r++) {
        int rr = r0 + r;
        if (rr < NN) O[rr*32 + tx] = acc[r];
    }
}

// ---------------- g_AUB = spmm(g_Y) ----------------
__global__ void k_spmm_aub() {
    int lane = threadIdx.x;
    int row  = blockIdx.x*blockDim.y + threadIdx.y;
    if (row >= NN) return;
    int e0 = g_rowptr[row], e1 = g_rowptr[row+1];
    float4 acc = gather_f(reinterpret_cast<const float4*>(g_Y), e0, e1, lane);
    reinterpret_cast<float4*>(g_AUB)[row*32 + lane] = acc;
}

// ---------------- persistent power iteration (8 iters, 1 launch) ----------------
__global__ __launch_bounds__(256) void k_powiter() {
    int tid = threadIdx.x, lane = tid & 31, wy = tid >> 5;
    int gw = blockIdx.x*8 + wy;
    const int totw = POWB*8;
    __shared__ double sd[8];
    int ph = 0;
    for (int it = 0; it < POW_ITERS; it++) {
        float scale;
        if (it == 0) scale = rsqrtf((float)NN);
        else         scale = (float)(1.0 / (sqrt(__ldcg(&g_nrm[it-1])) + 1e-12));
        const float* vin  = (it & 1) ? g_pu : g_pv;
        float*       vout = (it & 1) ? g_pv : g_pu;
        double wsum = 0.0;
        for (int row = gw; row < NN; row += totw) {
            int e0 = g_rowptr[row], e1 = g_rowptr[row+1];
            float s = 0.f;
            for (int e = e0 + lane; e < e1; e += 32) {
                float w = fabsf(g_wts[e]);
                float v = (it == 0) ? scale : vin[g_cols[e]] * scale;
                s += w * v;
            }
#pragma unroll
            for (int o = 16; o; o >>= 1) s += __shfl_down_sync(0xffffffffu, s, o);
            if (lane == 0) { vout[row] = s; wsum += (double)s * (double)s; }
        }
        if (lane == 0) sd[wy] = wsum;
        __syncthreads();
        if (tid == 0) {
            double t = 0.0;
#pragma unroll
            for (int j = 0; j < 8; j++) t += sd[j];
            atomicAdd(&g_nrm[it], t);
        }
        grid_barrier(&g_bar1, &g_phase1, ++ph, POWB);
    }
}

// ---------------- L-inf projection of W (warp-per-row bisection) ----------------
__global__ void k_proj(const float* __restrict__ W) {
    int lane = threadIdx.x & 31, wy = threadIdx.x >> 5;
    int row = blockIdx.x*4 + wy;
    if (row >= NH) return;
    float v = KAPPA / ((float)sqrt(g_nrm[POW_ITERS-1]) + 1e-5f);
    float w0 = W[row*NH + lane];
    float w1 = W[row*NH + 32 + lane];
    float w2 = W[row*NH + 64 + lane];
    float w3 = W[row*NH + 96 + lane];
    float a0 = fabsf(w0), a1 = fabsf(w1), a2 = fabsf(w2), a3 = fabsf(w3);
    float s = a0 + a1 + a2 + a3;
    float mx = fmaxf(fmaxf(a0, a1), fmaxf(a2, a3));
#pragma unroll
    for (int o = 16; o; o >>= 1) {
        s  += __shfl_xor_sync(0xffffffffu, s, o);
        mx  = fmaxf(mx, __shfl_xor_sync(0xffffffffu, mx, o));
    }
    float theta = 0.f;
    if (s > v) {
        float lo = 0.f, hi = mx;
#pragma unroll 2
        for (int i = 0; i < 50; i++) {
            float mid = 0.5f*(lo + hi);
            float t = fmaxf(a0-mid,0.f) + fmaxf(a1-mid,0.f) + fmaxf(a2-mid,0.f) + fmaxf(a3-mid,0.f);
#pragma unroll
            for (int o = 16; o; o >>= 1) t += __shfl_xor_sync(0xffffffffu, t, o);
            if (t > v) lo = mid; else hi = mid;
        }
        theta = fmaxf(0.5f*(lo + hi), 0.f);
    }
    float m0 = fmaxf(a0 - theta, 0.f);
    float m1 = fmaxf(a1 - theta, 0.f);
    float m2 = fmaxf(a2 - theta, 0.f);
    float m3 = fmaxf(a3 - theta, 0.f);
    g_Wp[row*NH + lane]      = (w0 > 0.f) ? m0 : ((w0 < 0.f) ? -m0 : 0.f);
    g_Wp[row*NH + 32 + lane] = (w1 > 0.f) ? m1 : ((w1 < 0.f) ? -m1 : 0.f);
    g_Wp[row*NH + 64 + lane] = (w2 > 0.f) ? m2 : ((w2 < 0.f) ? -m2 : 0.f);
    g_Wp[row*NH + 96 + lane] = (w3 > 0.f) ? m3 : ((w3 < 0.f) ? -m3 : 0.f);
}

__global__ void k_transV(const float* __restrict__ V) {
    int idx = blockIdx.x*blockDim.x + threadIdx.x;
    if (idx >= NC*NH) return;
    int c = idx / NH, k = idx % NH;
    g_Vt[k*NC + c] = V[idx];
}

// ---------------- persistent FUSED Picard solver + output ----------------
// Identity: spmm(z @ Wp) == spmm(z) @ Wp. Gather-first, then row-local
// vector-matrix against smem-resident Wp => ONE phase + ONE barrier per iter.
// Stage 0: gather fp16(Z);     Y = T@Wp; Z' = relu(Y + AUB)
// Stage 1: gather fp32 Z;      S = T@Wp; Z' = relu(S + AUB)   (exact transition)
// Stage 2: gather fp16(dZ);    S += T@Wp; Z' = relu(S + AUB)  (delta, linearity)
// Stop: adaptive check at ERR_TARGET=2e-3 (binding; measured tail rho ~0.55
// => stop res ~1.64e-3; calibrated transfer => rel_err ~6e-5..9e-5), plus
// absolute fallback res < 5e-4. Deterministic.
__global__ __launch_bounds__(PTHR, 2) void k_picard(float* __restrict__ out, int writez) {
    extern __shared__ float4 smdyn[];
    float4* sW4  = smdyn;                          // Wp: 4096 float4 = 64KB
    float*  tbuf = (float*)(smdyn + NH*32);        // 8 warps * 4 rows * 128 = 16KB
    double* sred = (double*)(tbuf + 8*4*128);      // 16 doubles
    int tid = threadIdx.x;
    int lane = tid & 31, wy = tid >> 5;            // 8 warps
    float* tb = tbuf + wy*512;
    int ph = 0;
    const int totw = PBLK*8;

    for (int t = tid; t < NH*32; t += PTHR)        // Wp resident for whole solve
        sW4[t] = reinterpret_cast<const float4*>(g_Wp)[t];

    // init: Z0 = relu(AUB) into buffer A (g_Z) + fp16 pack into Xh[0]
    for (int i = blockIdx.x*PTHR + tid; i < DTOT/4; i += PBLK*PTHR) {
        float4 b = reinterpret_cast<const float4*>(g_AUB)[i];
        float4 f = make_float4(fmaxf(b.x,0.f), fmaxf(b.y,0.f), fmaxf(b.z,0.f), fmaxf(b.w,0.f));
        reinterpret_cast<float4*>(g_Z)[i] = f;
        g_Xh[0][i] = pack_h4(f);
    }
    grid_barrier(&g_bar2, &g_phase2, ++ph, PBLK);

    int stage = 0;
    int cur = 0;
    double prev_r2 = 0.0;
    const float* zfin = g_Z;
    for (int it = 1; it < MAX_ITERS; it++) {
        int nxt = cur ^ 1;
        const float4* Zc = reinterpret_cast<const float4*>(cur ? g_Y : g_Z);
        float4*       Zn = reinterpret_cast<float4*>(nxt ? g_Y : g_Z);
        const uint2*  Xc = g_Xh[cur];
        uint2*        Xn = g_Xh[nxt];

        float tr2 = 0.f, tn2 = 0.f;
        for (int chunk = blockIdx.x*8 + wy; chunk < NCHUNK; chunk += totw) {
            int rowb = chunk*4;
            float4 acc[4];
            // ---- gather T = (A * operand) for 4 consecutive rows ----
            if (stage == 1) {
#pragma unroll
                for (int r = 0; r < 4; r++) {
                    int row = rowb + r;
                    acc[r] = gather_f(Zc, g_rowptr[row], g_rowptr[row+1], lane);
                }
            } else {
#pragma unroll
                for (int r = 0; r < 4; r++) {
                    int row = rowb + r;
                    acc[r] = gather_h(Xc, g_rowptr[row], g_rowptr[row+1], lane);
                }
            }
            // ---- stage T into smem, then row-local vecmat: Y = T @ Wp ----
#pragma unroll
            for (int r = 0; r < 4; r++)
                reinterpret_cast<float4*>(tb + r*128)[lane] = acc[r];
            __syncwarp();
            float4 o0 = make_float4(0.f,0.f,0.f,0.f);
            float4 o1 = o0, o2 = o0, o3 = o0;
#pragma unroll 4
            for (int k = 0; k < 128; k++) {
                float4 w4 = sW4[k*32 + lane];
                o0 = make_float4(fmaf(tb[k], w4.x, o0.x), fmaf(tb[k], w4.y, o0.y),
                                 fmaf(tb[k], w4.z, o0.z), fmaf(tb[k], w4.w, o0.w));
                float t1 = tb[128 + k];
                o1 = make_float4(fmaf(t1, w4.x, o1.x), fmaf(t1, w4.y, o1.y),
                                 fmaf(t1, w4.z, o1.z), fmaf(t1, w4.w, o1.w));
                float t2 = tb[256 + k];
                o2 = make_float4(fmaf(t2, w4.x, o2.x), fmaf(t2, w4.y, o2.y),
                                 fmaf(t2, w4.z, o2.z), fmaf(t2, w4.w, o2.w));
                float t3 = tb[384 + k];
                o3 = make_float4(fmaf(t3, w4.x, o3.x), fmaf(t3, w4.y, o3.y),
                                 fmaf(t3, w4.z, o3.z), fmaf(t3, w4.w, o3.w));
            }
            __syncwarp();
            float4 ov[4] = {o0, o1, o2, o3};
            // ---- epilogue per row ----
#pragma unroll
            for (int r = 0; r < 4; r++) {
                int o = (rowb + r)*32 + lane;
                float4 b = reinterpret_cast<const float4*>(g_AUB)[o];
                float4 y = ov[r];
                float4 s4, f;
                if (stage == 0) {
                    f.x = fmaxf(y.x + b.x, 0.f);
                    f.y = fmaxf(y.y + b.y, 0.f);
                    f.z = fmaxf(y.z + b.z, 0.f);
                    f.w = fmaxf(y.w + b.w, 0.f);
                } else {
                    if (stage == 1) s4 = y;
                    else {
                        s4 = reinterpret_cast<const float4*>(g_S)[o];
                        s4.x += y.x; s4.y += y.y; s4.z += y.z; s4.w += y.w;
                    }
                    reinterpret_cast<float4*>(g_S)[o] = s4;
                    f.x = fmaxf(s4.x + b.x, 0.f);
                    f.y = fmaxf(s4.y + b.y, 0.f);
                    f.z = fmaxf(s4.z + b.z, 0.f);
                    f.w = fmaxf(s4.w + b.w, 0.f);
                }
                float4 zo = Zc[o];
                Zn[o] = f;
                float dx = f.x - zo.x, dy = f.y - zo.y, dz = f.z - zo.z, dw = f.w - zo.w;
                // operand for the NEXT iteration
                if (stage == 0) Xn[o] = pack_h4(f);
                else            Xn[o] = pack_h4(make_float4(dx, dy, dz, dw));
                tr2 += dx*dx + dy*dy + dz*dz + dw*dw;
                tn2 += f.x*f.x + f.y*f.y + f.z*f.z + f.w*f.w;
            }
        }
#pragma unroll
        for (int off = 16; off; off >>= 1) {
            tr2 += __shfl_down_sync(0xffffffffu, tr2, off);
            tn2 += __shfl_down_sync(0xffffffffu, tn2, off);
        }
        if (lane == 0) { sred[wy] = (double)tr2; sred[8+wy] = (double)tn2; }
        __syncthreads();
        if (tid == 0) {
            double a = 0.0, b = 0.0;
#pragma unroll
            for (int j = 0; j < 8; j++) { a += sred[j]; b += sred[8+j]; }
            atomicAdd(&g_r2[it], a);
            atomicAdd(&g_n2[it], b);
        }
        grid_barrier(&g_bar2, &g_phase2, ++ph, PBLK);

        zfin = nxt ? g_Y : g_Z;
        cur = nxt;
        double r2 = __ldcg(&g_r2[it]);
        double n2 = __ldcg(&g_n2[it]);
        if (stage == 0) {
            if (r2 < SWITCH_TOL2 * n2 || it >= STAGEA_CAP) stage = 1;
        } else {
            bool stop = (r2 < STOP_TOL2 * n2);
            if (prev_r2 > 0.0) {
                double rho = sqrt(r2 / prev_r2);
                double rc  = fmin(0.9, fmax(0.55, rho * 1.15));
                double th  = ERR_TARGET * (1.0 - rc) / rc;
                if (r2 < th * th * n2) stop = true;
            }
            if (stop) break;
            if (stage == 1) stage = 2;
            prev_r2 = r2;
        }
    }

    // ---------- fused output: label = Zfin @ V^T (+ optional z copy) ----------
    for (int row = blockIdx.x*8 + wy; row < NN; row += totw) {
        const float* z = zfin + row*NH;
        float acc0 = 0.f, acc1 = 0.f;
#pragma unroll 8
        for (int k = 0; k < NH; k++) {
            float zv = z[k];
            acc0 = fmaf(zv, g_Vt[k*NC + lane], acc0);
            if (lane < 8) acc1 = fmaf(zv, g_Vt[k*NC + 32 + lane], acc1);
        }
        out[row*NC + lane] = acc0;
        if (lane < 8) out[row*NC + 32 + lane] = acc1;
        if (writez) {
            float4 zz = reinterpret_cast<const float4*>(zfin)[row*32 + lane];
            reinterpret_cast<float4*>(out + NN*NC)[row*32 + lane] = zz;
        }
    }
}

// ---------------- launcher ----------------
extern "C" void kernel_launch(void* const* d_in, const int* in_sizes, int n_in,
                              void* d_out, int out_size) {
    const float* U  = nullptr;
    const void*  ei = nullptr;
    const float* ew = nullptr;
    const float* W  = nullptr;
    const float* B  = nullptr;
    const float* V  = nullptr;
    for (int i = 0; i < n_in; i++) {
        switch (in_sizes[i]) {
            case 7680000: U  = (const float*)d_in[i]; break;
            case 1920000: ei = d_in[i];               break;
            case  960000: ew = (const float*)d_in[i]; break;
            case   16384: W  = (const float*)d_in[i]; break;
            case   32768: B  = (const float*)d_in[i]; break;
            case    5120: V  = (const float*)d_in[i]; break;
            default: break;
        }
    }
    if (!U || !ei || !ew || !W || !B || !V) {
        U  = (const float*)d_in[0];
        ei = d_in[1];
        ew = (const float*)d_in[2];
        W  = (const float*)d_in[3];
        B  = (const float*)d_in[4];
        V  = (const float*)d_in[5];
    }
    float* out = (float*)d_out;

    static int init_done = 0;
    static cudaStream_t s1, s2;
    static cudaEvent_t evStart, evGemm, evCSR, evPow;
    const int picard_smem = NH*32*16 + 8*4*128*4 + 16*8;  // Wp 64KB + tbuf 16KB + red
    if (!init_done) {
        cudaFuncSetAttribute(k_picard, cudaFuncAttributeMaxDynamicSharedMemorySize, picard_smem);
        cudaStreamCreateWithFlags(&s1, cudaStreamNonBlocking);
        cudaStreamCreateWithFlags(&s2, cudaStreamNonBlocking);
        cudaEventCreateWithFlags(&evStart, cudaEventDisableTiming);
        cudaEventCreateWithFlags(&evGemm, cudaEventDisableTiming);
        cudaEventCreateWithFlags(&evCSR, cudaEventDisableTiming);
        cudaEventCreateWithFlags(&evPow, cudaEventDisableTiming);
        init_done = 1;
    }

    dim3 spmmBlk(32, 8);
    int  spmmGrid = (NN + 7) / 8;
    dim3 gemmBlk(32, 4);
    int  gemmGrid = (NN + 31) / 32;

    // fork the U@B GEMM at t=0 (depends only on inputs; FMA-bound, overlaps
    // the atomics/ALU-bound CSR build on complementary pipes)
    cudaEventRecord(evStart, 0);
    cudaStreamWaitEvent(s1, evStart, 0);
    k_gemm_setup<NF><<<gemmGrid, gemmBlk, 0, s1>>>(U, B);
    cudaEventRecord(evGemm, s1);

    // CSR build on the main stream
    k_zero_small<<<(NN + 255)/256, 256>>>();
    k_detect<<<1, 256>>>((const unsigned int*)ei);
    k_convert_hist<<<(NE + 255)/256, 256>>>(ei);
    k_scan1<<<SCANB, 1024>>>();
    k_scan2<<<SCANB, 1024>>>();
    k_scatter<<<(NE + 255)/256, 256>>>(ew);
    cudaEventRecord(evCSR, 0);

    // fork power iteration after CSR (overlaps spmm_aub)
    cudaStreamWaitEvent(s2, evCSR, 0);
    k_powiter<<<POWB, 256, 0, s2>>>();
    cudaEventRecord(evPow, s2);

    // AUB = spmm(U@B): needs both CSR (main) and the forked GEMM
    cudaStreamWaitEvent(0, evGemm, 0);
    k_spmm_aub<<<spmmGrid, spmmBlk>>>();

    // projection needs rho
    cudaStreamWaitEvent(0, evPow, 0);
    k_proj<<<32, 128>>>(W);
    k_transV<<<(NC*NH + 127)/128, 128>>>(V);

    // fused persistent Picard solver (one phase + one barrier per iteration)
    int writez = (out_size >= NN*NC + DTOT) ? 1 : 0;
    k_picard<<<PBLK, PTHR, picard_smem>>>(out, writez);
}